// round 16
// baseline (speedup 1.0000x reference)
#include <cuda_runtime.h>
#include <cuda_fp16.h>
#include <cstdint>

#define BB 8
#define TT 200
#define UU 100
#define JJ 640
#define VV 1024
#define MM (BB*TT*UU)          // 160000 output rows

// GEMM tiling (round-9 validated config — frozen)
#define TILE_M 128
#define TILE_N 256
#define BK     32
#define NCHUNK (JJ/BK)         // 20
#define NSTAGE 4
#define NTILE_X (VV/TILE_N)    // 4
#define NTILE_Y (MM/TILE_M)    // 1250
#define NTILES_TOT (NTILE_X*NTILE_Y)   // 5000
#define LDAH   40              // halves per smem row (80B pitch, conflict-free ldsm)
#define A_BUF  (TILE_M*LDAH)   // 5120 halves
#define B_BUF  (TILE_N*LDAH)   // 10240 halves
#define STAGE_H (A_BUF + B_BUF)              // 15360 halves per stage
#define SMEM_BYTES (NSTAGE*STAGE_H*2)        // 122880

#define WT_CTAS 640            // wt blocks prepended to act grid

// scratch
__device__ float  g_enc [BB*TT*JJ];
__device__ float  g_pred[BB*UU*JJ];
__device__ __half g_wt  [VV*JJ];                 // W_out^T fp16: [v][j]
__device__ __half g_act [(size_t)MM*JJ];         // tanh(enc+pred) fp16

// ---------------------------------------------------------------------------
// helpers
// ---------------------------------------------------------------------------
__device__ __forceinline__ uint32_t smem_u32(const void* p) {
    uint32_t a;
    asm("{ .reg .u64 t; cvta.to.shared.u64 t, %1; cvt.u32.u64 %0, t; }" : "=r"(a) : "l"(p));
    return a;
}
__device__ __forceinline__ float fast_tanh(float x) {
    float e, r;
    asm("ex2.approx.f32 %0, %1;" : "=f"(e) : "f"(x * 2.885390081777927f));
    asm("rcp.approx.f32 %0, %1;" : "=f"(r) : "f"(e + 1.0f));
    return (e - 1.0f) * r;
}
__device__ __forceinline__ void cp16(uint32_t s, const void* g) {
    asm volatile("cp.async.cg.shared.global [%0], [%1], 16;" :: "r"(s), "l"(g));
}
__device__ __forceinline__ void cp_commit() {
    asm volatile("cp.async.commit_group;" ::: "memory");
}
__device__ __forceinline__ void cp_wait2() {
    asm volatile("cp.async.wait_group 2;" ::: "memory");
}
__device__ __forceinline__ void ldsm4(uint32_t* r, const __half* p) {
    uint32_t a = smem_u32(p);
    asm volatile("ldmatrix.sync.aligned.m8n8.x4.shared.b16 {%0,%1,%2,%3}, [%4];"
                 : "=r"(r[0]), "=r"(r[1]), "=r"(r[2]), "=r"(r[3]) : "r"(a));
}
__device__ __forceinline__ void mma16816(float* c, const uint32_t* a, const uint32_t* b) {
    asm volatile(
        "mma.sync.aligned.m16n8k16.row.col.f32.f16.f16.f32 "
        "{%0,%1,%2,%3}, {%4,%5,%6,%7}, {%8,%9}, {%0,%1,%2,%3};"
        : "+f"(c[0]), "+f"(c[1]), "+f"(c[2]), "+f"(c[3])
        : "r"(a[0]), "r"(a[1]), "r"(a[2]), "r"(a[3]), "r"(b[0]), "r"(b[1]));
}

// ---------------------------------------------------------------------------
// merged prejoint projections — double-buffered, 1 barrier/iter, k-step 32
// enc: 250 CTAs (10 x 25), pred: 130 CTAs (10 x 13)
// ---------------------------------------------------------------------------
#define PJ_LD 68
__global__ void __launch_bounds__(256) proj2_kernel(
    const float* __restrict__ enc_out, const float* __restrict__ pred_out,
    const float* __restrict__ W_enc, const float* __restrict__ W_pred,
    const float* __restrict__ b_enc,
    float* __restrict__ ge, float* __restrict__ gp)
{
    const int N = 640, K = 640;
    __shared__ float Xs[2][32][PJ_LD];
    __shared__ float Ws[2][32][PJ_LD];
    const int tid = threadIdx.x;
    const int tx = tid & 15, ty = tid >> 4;

    const float *X, *W, *bias;
    float* P;
    int M, row0, col0;
    if (blockIdx.x < 250) {
        X = enc_out; W = W_enc; bias = b_enc; P = ge; M = BB * TT;
        col0 = (blockIdx.x % 10) * 64; row0 = (blockIdx.x / 10) * 64;
    } else {
        int t = blockIdx.x - 250;
        X = pred_out; W = W_pred; bias = nullptr; P = gp; M = BB * UU;
        col0 = (t % 10) * 64; row0 = (t / 10) * 64;
    }

    const int xk = tid & 31, xm8 = tid >> 5;
    const int wn = tid & 63, wk4 = tid >> 6;

    float acc[4][4];
#pragma unroll
    for (int i = 0; i < 4; i++)
#pragma unroll
        for (int j = 0; j < 4; j++) acc[i][j] = 0.f;

    float gx[8], gw[8];
#pragma unroll
    for (int p = 0; p < 8; p++) {
        int gr = row0 + xm8 + p * 8;
        gx[p] = (gr < M) ? X[(size_t)gr * K + xk] : 0.f;
        gw[p] = W[(size_t)(wk4 + p * 4) * N + col0 + wn];
    }
#pragma unroll
    for (int p = 0; p < 8; p++) {
        Xs[0][xk][xm8 + p * 8] = gx[p];
        Ws[0][wk4 + p * 4][wn] = gw[p];
    }
    __syncthreads();

    const int NIT = K / 32;
    for (int it = 0; it < NIT; it++) {
        const int cur = it & 1;
        if (it + 1 < NIT) {
            const int k0 = (it + 1) * 32;
#pragma unroll
            for (int p = 0; p < 8; p++) {
                int gr = row0 + xm8 + p * 8;
                gx[p] = (gr < M) ? X[(size_t)gr * K + k0 + xk] : 0.f;
                gw[p] = W[(size_t)(k0 + wk4 + p * 4) * N + col0 + wn];
            }
        }
#pragma unroll
        for (int k = 0; k < 32; k++) {
            float4 av = *(const float4*)&Xs[cur][k][ty * 4];
            float4 bv = *(const float4*)&Ws[cur][k][tx * 4];
            float a4[4] = {av.x, av.y, av.z, av.w};
            float b4[4] = {bv.x, bv.y, bv.z, bv.w};
#pragma unroll
            for (int i = 0; i < 4; i++)
#pragma unroll
                for (int j = 0; j < 4; j++) acc[i][j] += a4[i] * b4[j];
        }
        if (it + 1 < NIT) {
            const int nxt = cur ^ 1;
#pragma unroll
            for (int p = 0; p < 8; p++) {
                Xs[nxt][xk][xm8 + p * 8] = gx[p];
                Ws[nxt][wk4 + p * 4][wn] = gw[p];
            }
        }
        __syncthreads();
    }

#pragma unroll
    for (int i = 0; i < 4; i++) {
        int gr = row0 + ty * 4 + i;
        if (gr < M) {
            int gc = col0 + tx * 4;
            float4 o;
            if (bias) {
                float4 bv = *(const float4*)&bias[gc];
                o.x = acc[i][0] + bv.x; o.y = acc[i][1] + bv.y;
                o.z = acc[i][2] + bv.z; o.w = acc[i][3] + bv.w;
            } else {
                o.x = acc[i][0]; o.y = acc[i][1];
                o.z = acc[i][2]; o.w = acc[i][3];
            }
            *(float4*)&P[(size_t)gr * N + gc] = o;
        }
    }
}

// ---------------------------------------------------------------------------
// merged act + wt kernel: CTAs [0, WT_CTAS) transpose W_out -> fp16,
// CTAs [WT_CTAS, ...) compute act[row][j] = fp16(tanh(enc+pred))
// ---------------------------------------------------------------------------
__global__ void __launch_bounds__(256) actwt_kernel(
    const float* __restrict__ enc, const float* __restrict__ pred,
    const float* __restrict__ W, __half* __restrict__ act,
    __half* __restrict__ Wt)
{
    __shared__ float tile[32][33];

    if (blockIdx.x < WT_CTAS) {
        int t = blockIdx.x;
        int v0 = (t & 31) * 32, j0 = (t >> 5) * 32;
        int tx = threadIdx.x & 31, ty = threadIdx.x >> 5;
#pragma unroll
        for (int i = 0; i < 4; i++)
            tile[ty + i * 8][tx] = W[(j0 + ty + i * 8) * VV + v0 + tx];
        __syncthreads();
#pragma unroll
        for (int i = 0; i < 4; i++)
            Wt[(size_t)(v0 + ty + i * 8) * JJ + j0 + tx] = __float2half_rn(tile[tx][ty + i * 8]);
        return;
    }

    int idx = (blockIdx.x - WT_CTAS) * 256 + threadIdx.x;
    int row = idx / 80;
    int jc  = (idx % 80) * 8;
    int bt  = row / UU;
    int b   = row / (TT * UU);
    int u   = row % UU;

    const float4* ep = (const float4*)&enc [(size_t)bt * JJ + jc];
    const float4* pp = (const float4*)&pred[(size_t)(b * UU + u) * JJ + jc];
    float4 e0 = ep[0], e1 = ep[1];
    float4 p0 = pp[0], p1 = pp[1];

    __half2 h[4];
    h[0] = __floats2half2_rn(fast_tanh(e0.x + p0.x), fast_tanh(e0.y + p0.y));
    h[1] = __floats2half2_rn(fast_tanh(e0.z + p0.z), fast_tanh(e0.w + p0.w));
    h[2] = __floats2half2_rn(fast_tanh(e1.x + p1.x), fast_tanh(e1.y + p1.y));
    h[3] = __floats2half2_rn(fast_tanh(e1.z + p1.z), fast_tanh(e1.w + p1.w));
    *(uint4*)&act[(size_t)row * JJ + jc] = *(uint4*)h;
}

// ---------------------------------------------------------------------------
// persistent GEMM: 512 thr, 16 warps (4x4), warp tile 32x64, CTA 128x256
// 4-stage cross-tile cp.async pipeline; prefetch uses incremental state
// (no division / address recompute per chunk — ALU cut)
// ---------------------------------------------------------------------------
__global__ void __launch_bounds__(512, 1) gemm_kernel(
    const __half* __restrict__ A, const __half* __restrict__ Bt,
    const float* __restrict__ bias, float* __restrict__ out, int grid_sz)
{
    extern __shared__ __half sm[];

    const int tid  = threadIdx.x;
    const int lane = tid & 31, wid = tid >> 5;
    const int warp_m = wid >> 2, warp_n = wid & 3;     // 4 x 4 warp grid
    const int bid = blockIdx.x;

    // per-thread cp.async lane: r in [0,128), c4 in [0,4)
    const int r = tid >> 2, c4 = tid & 3;
    const uint32_t smbase = smem_u32(sm);
    const uint32_t cpA_off = (uint32_t)(r * LDAH + c4 * 8) * 2;
    const uint32_t cpB_off = (uint32_t)(A_BUF + r * LDAH + c4 * 8) * 2;
    const uint32_t brow2 = (uint32_t)(128 * LDAH) * 2;

    // incremental prefetch state (call #k targets global chunk k; stage k&3)
    int pf_q = 0;                 // call counter (== target chunk index)
    int pf_c = 0;                 // chunk within prefetch tile
    int pf_tile = bid;            // tile being prefetched
    const __half* pfA = A  + ((size_t)(bid >> 2) * TILE_M + r) * JJ + c4 * 8;
    const __half* pfB = Bt + ((size_t)(bid & 3) * TILE_N + r) * JJ + c4 * 8;

    auto prefetch = [&]() {
        if (pf_tile < NTILES_TOT) {
            const uint32_t stg = smbase + (uint32_t)((pf_q & (NSTAGE - 1)) * STAGE_H) * 2;
            cp16(stg + cpA_off, pfA);
            cp16(stg + cpB_off, pfB);
            cp16(stg + cpB_off + brow2, pfB + (size_t)128 * JJ);
            pfA += BK;
            pfB += BK;
        }
        cp_commit();              // always commit to keep group accounting
        pf_q++;
        if (++pf_c == NCHUNK) {
            pf_c = 0;
            pf_tile += grid_sz;
            if (pf_tile < NTILES_TOT) {
                pfA = A  + ((size_t)(pf_tile >> 2) * TILE_M + r) * JJ + c4 * 8;
                pfB = Bt + ((size_t)(pf_tile & 3) * TILE_N + r) * JJ + c4 * 8;
            }
        }
    };

    // prologue: chunks 0..2
#pragma unroll
    for (int s = 0; s < NSTAGE - 1; s++) prefetch();

    // ldsm lane decode (validated mapping)
    const int g = lane >> 3, lr = lane & 7;
    const int a_row_off = lr + ((g & 1) << 3);
    const int a_col_off = (g >> 1) << 3;
    const int b_row_off = lr + ((g >> 1) << 3);
    const int b_col_off = (g & 1) << 3;

    const int a_base_row = warp_m * 32 + a_row_off;
    const int b_base_row = warp_n * 64 + b_row_off;

    uint32_t afr[2][2][4];     // [ks][mi]
    uint32_t bfrL[2][4][2];    // [ks][nj 0..3]
    uint32_t bfrH[4][2];       // nj 4..7 (single-buffered, WAR reuse)

    int q = 0;
    for (int tile = bid; tile < NTILES_TOT; tile += grid_sz) {
        const size_t m0 = (size_t)(tile >> 2) * TILE_M;
        const int n0 = (tile & 3) * TILE_N;

        float acc[2][8][4];
#pragma unroll
        for (int i = 0; i < 2; i++)
#pragma unroll
            for (int j = 0; j < 8; j++)
#pragma unroll
                for (int p = 0; p < 4; p++) acc[i][j][p] = 0.f;

        for (int c = 0; c < NCHUNK; c++, q++) {
            cp_wait2();
            __syncthreads();

            const __half* As = sm + (q & (NSTAGE - 1)) * STAGE_H;
            const __half* Bs = As + A_BUF;

            // ---- ks = 0 loads ----
#pragma unroll
            for (int mi = 0; mi < 2; mi++)
                ldsm4(afr[0][mi], &As[(a_base_row + mi * 16) * LDAH + a_col_off]);
#pragma unroll
            for (int j = 0; j < 2; j++) {
                uint32_t r4[4];
                ldsm4(r4, &Bs[(b_base_row + j * 16) * LDAH + b_col_off]);
                bfrL[0][2 * j][0] = r4[0]; bfrL[0][2 * j][1] = r4[1];
                bfrL[0][2 * j + 1][0] = r4[2]; bfrL[0][2 * j + 1][1] = r4[3];
            }
#pragma unroll
            for (int j = 0; j < 2; j++) {
                uint32_t r4[4];
                ldsm4(r4, &Bs[(b_base_row + (j + 2) * 16) * LDAH + b_col_off]);
                bfrH[2 * j][0] = r4[0]; bfrH[2 * j][1] = r4[1];
                bfrH[2 * j + 1][0] = r4[2]; bfrH[2 * j + 1][1] = r4[3];
            }

            // mma ks0 x low half, while loading ks1 A + BL
#pragma unroll
            for (int mi = 0; mi < 2; mi++)
#pragma unroll
                for (int nj = 0; nj < 4; nj++)
                    mma16816(acc[mi][nj], afr[0][mi], bfrL[0][nj]);

#pragma unroll
            for (int mi = 0; mi < 2; mi++)
                ldsm4(afr[1][mi], &As[(a_base_row + mi * 16) * LDAH + 16 + a_col_off]);
#pragma unroll
            for (int j = 0; j < 2; j++) {
                uint32_t r4[4];
                ldsm4(r4, &Bs[(b_base_row + j * 16) * LDAH + 16 + b_col_off]);
                bfrL[1][2 * j][0] = r4[0]; bfrL[1][2 * j][1] = r4[1];
                bfrL[1][2 * j + 1][0] = r4[2]; bfrL[1][2 * j + 1][1] = r4[3];
            }

            // mma ks0 x high half
#pragma unroll
            for (int mi = 0; mi < 2; mi++)
#pragma unroll
                for (int nj = 0; nj < 4; nj++)
                    mma16816(acc[mi][nj + 4], afr[0][mi], bfrH[nj]);

            // load ks1 BH (WAR reuse)
#pragma unroll
            for (int j = 0; j < 2; j++) {
                uint32_t r4[4];
                ldsm4(r4, &Bs[(b_base_row + (j + 2) * 16) * LDAH + 16 + b_col_off]);
                bfrH[2 * j][0] = r4[0]; bfrH[2 * j][1] = r4[1];
                bfrH[2 * j + 1][0] = r4[2]; bfrH[2 * j + 1][1] = r4[3];
            }

            // mma ks1 x low half
#pragma unroll
            for (int mi = 0; mi < 2; mi++)
#pragma unroll
                for (int nj = 0; nj < 4; nj++)
                    mma16816(acc[mi][nj], afr[1][mi], bfrL[1][nj]);

            // issue prefetch for chunk q+3 (incremental state)
            prefetch();

            // mma ks1 x high half
#pragma unroll
            for (int mi = 0; mi < 2; mi++)
#pragma unroll
                for (int nj = 0; nj < 4; nj++)
                    mma16816(acc[mi][nj + 4], afr[1][mi], bfrH[nj]);
        }

        // epilogue (registers only; overlaps in-flight next-tile cp.async)
        const int qr = lane >> 2, qc = (lane & 3) * 2;
        const int colbase = n0 + warp_n * 64;
#pragma unroll
        for (int mi = 0; mi < 2; mi++) {
            size_t row = m0 + warp_m * 32 + mi * 16 + qr;
            float* o0 = out + row * VV + colbase;
            float* o1 = o0 + (size_t)8 * VV;
#pragma unroll
            for (int nj = 0; nj < 8; nj++) {
                int col = nj * 8 + qc;
                float2 bv = *(const float2*)&bias[colbase + col];
                float2 w0 = { acc[mi][nj][0] + bv.x, acc[mi][nj][1] + bv.y };
                float2 w1 = { acc[mi][nj][2] + bv.x, acc[mi][nj][3] + bv.y };
                *(float2*)(o0 + col) = w0;
                *(float2*)(o1 + col) = w1;
            }
        }
    }
}

// ---------------------------------------------------------------------------
extern "C" void kernel_launch(void* const* d_in, const int* in_sizes, int n_in,
                              void* d_out, int out_size)
{
    const float* enc_out  = (const float*)d_in[0];
    const float* pred_out = (const float*)d_in[1];
    const float* W_enc    = (const float*)d_in[2];
    const float* b_enc    = (const float*)d_in[3];
    const float* W_pred   = (const float*)d_in[4];
    const float* W_out    = (const float*)d_in[5];
    const float* b_out    = (const float*)d_in[6];
    float* out = (float*)d_out;

    float *ge, *gp; __half *gw, *ga;
    cudaGetSymbolAddress((void**)&ge, g_enc);
    cudaGetSymbolAddress((void**)&gp, g_pred);
    cudaGetSymbolAddress((void**)&gw, g_wt);
    cudaGetSymbolAddress((void**)&ga, g_act);

    int nsm = 148;
    cudaDeviceGetAttribute(&nsm, cudaDevAttrMultiProcessorCount, 0);

    proj2_kernel<<<380, 256>>>(enc_out, pred_out, W_enc, W_pred, b_enc, ge, gp);
    actwt_kernel<<<WT_CTAS + (MM * 80) / 256, 256>>>(ge, gp, W_out, ga, gw);

    cudaFuncSetAttribute(gemm_kernel, cudaFuncAttributeMaxDynamicSharedMemorySize, SMEM_BYTES);
    gemm_kernel<<<nsm, 512, SMEM_BYTES>>>(ga, gw, b_out, out, nsm);
}

// round 17
// speedup vs baseline: 1.0806x; 1.0806x over previous
#include <cuda_runtime.h>
#include <cuda_fp16.h>
#include <cstdint>

#define BB 8
#define TT 200
#define UU 100
#define JJ 640
#define VV 1024
#define MM (BB*TT*UU)          // 160000 output rows

// GEMM tiling (round-9 validated config — frozen)
#define TILE_M 128
#define TILE_N 256
#define BK     32
#define NCHUNK (JJ/BK)         // 20
#define NSTAGE 4
#define NTILE_X (VV/TILE_N)    // 4
#define NTILE_Y (MM/TILE_M)    // 1250
#define NTILES_TOT (NTILE_X*NTILE_Y)   // 5000
#define LDAH   40              // halves per smem row (80B pitch, conflict-free ldsm)
#define A_BUF  (TILE_M*LDAH)   // 5120 halves
#define B_BUF  (TILE_N*LDAH)   // 10240 halves
#define STAGE_H (A_BUF + B_BUF)              // 15360 halves per stage
#define SMEM_BYTES (NSTAGE*STAGE_H*2)        // 122880

// scratch
__device__ float  g_enc [BB*TT*JJ];
__device__ float  g_pred[BB*UU*JJ];
__device__ __half g_wt  [VV*JJ];                 // W_out^T fp16: [v][j]
__device__ __half g_act [(size_t)MM*JJ];         // tanh(enc+pred) fp16

// ---------------------------------------------------------------------------
// helpers
// ---------------------------------------------------------------------------
__device__ __forceinline__ uint32_t smem_u32(const void* p) {
    uint32_t a;
    asm("{ .reg .u64 t; cvta.to.shared.u64 t, %1; cvt.u32.u64 %0, t; }" : "=r"(a) : "l"(p));
    return a;
}
__device__ __forceinline__ float hw_tanh(float x) {
    float r;
    asm("tanh.approx.f32 %0, %1;" : "=f"(r) : "f"(x));
    return r;
}
__device__ __forceinline__ void cp16(uint32_t s, const void* g) {
    asm volatile("cp.async.cg.shared.global [%0], [%1], 16;" :: "r"(s), "l"(g));
}
__device__ __forceinline__ void cp_commit() {
    asm volatile("cp.async.commit_group;" ::: "memory");
}
__device__ __forceinline__ void cp_wait2() {
    asm volatile("cp.async.wait_group 2;" ::: "memory");
}
__device__ __forceinline__ void ldsm4(uint32_t* r, const __half* p) {
    uint32_t a = smem_u32(p);
    asm volatile("ldmatrix.sync.aligned.m8n8.x4.shared.b16 {%0,%1,%2,%3}, [%4];"
                 : "=r"(r[0]), "=r"(r[1]), "=r"(r[2]), "=r"(r[3]) : "r"(a));
}
__device__ __forceinline__ void mma16816(float* c, const uint32_t* a, const uint32_t* b) {
    asm volatile(
        "mma.sync.aligned.m16n8k16.row.col.f32.f16.f16.f32 "
        "{%0,%1,%2,%3}, {%4,%5,%6,%7}, {%8,%9}, {%0,%1,%2,%3};"
        : "+f"(c[0]), "+f"(c[1]), "+f"(c[2]), "+f"(c[3])
        : "r"(a[0]), "r"(a[1]), "r"(a[2]), "r"(a[3]), "r"(b[0]), "r"(b[1]));
}

// ---------------------------------------------------------------------------
// merged prejoint projections (round-9 validated: 380 CTAs)
// ---------------------------------------------------------------------------
__global__ void __launch_bounds__(256) proj2_kernel(
    const float* __restrict__ enc_out, const float* __restrict__ pred_out,
    const float* __restrict__ W_enc, const float* __restrict__ W_pred,
    const float* __restrict__ b_enc,
    float* __restrict__ ge, float* __restrict__ gp)
{
    const int N = 640, K = 640;
    __shared__ float Xs[16][68];
    __shared__ float Ws[16][68];
    const int tid = threadIdx.x;
    const int tx = tid & 15, ty = tid >> 4;

    const float *X, *W, *bias;
    float* P;
    int M, row0, col0;
    if (blockIdx.x < 250) {
        X = enc_out; W = W_enc; bias = b_enc; P = ge; M = BB * TT;
        col0 = (blockIdx.x % 10) * 64; row0 = (blockIdx.x / 10) * 64;
    } else {
        int t = blockIdx.x - 250;
        X = pred_out; W = W_pred; bias = nullptr; P = gp; M = BB * UU;
        col0 = (t % 10) * 64; row0 = (t / 10) * 64;
    }

    float acc[4][4];
#pragma unroll
    for (int i = 0; i < 4; i++)
#pragma unroll
        for (int j = 0; j < 4; j++) acc[i][j] = 0.f;

    for (int k0 = 0; k0 < K; k0 += 16) {
        {
            int k = tid & 15, m = tid >> 4;
#pragma unroll
            for (int p = 0; p < 4; p++) {
                int mm = m + p * 16;
                int gr = row0 + mm;
                Xs[k][mm] = (gr < M) ? X[gr * K + k0 + k] : 0.f;
            }
        }
        {
            int n = tid & 63, kk = tid >> 6;
#pragma unroll
            for (int p = 0; p < 4; p++)
                Ws[kk + p * 4][n] = W[(k0 + kk + p * 4) * N + col0 + n];
        }
        __syncthreads();
#pragma unroll
        for (int k = 0; k < 16; k++) {
            float4 av = *(const float4*)&Xs[k][ty * 4];
            float4 bv = *(const float4*)&Ws[k][tx * 4];
            float a4[4] = {av.x, av.y, av.z, av.w};
            float b4[4] = {bv.x, bv.y, bv.z, bv.w};
#pragma unroll
            for (int i = 0; i < 4; i++)
#pragma unroll
                for (int j = 0; j < 4; j++) acc[i][j] += a4[i] * b4[j];
        }
        __syncthreads();
    }
#pragma unroll
    for (int i = 0; i < 4; i++) {
        int gr = row0 + ty * 4 + i;
        if (gr < M) {
            int gc = col0 + tx * 4;
            float4 o;
            if (bias) {
                float4 bv = *(const float4*)&bias[gc];
                o.x = acc[i][0] + bv.x; o.y = acc[i][1] + bv.y;
                o.z = acc[i][2] + bv.z; o.w = acc[i][3] + bv.w;
            } else {
                o.x = acc[i][0]; o.y = acc[i][1];
                o.z = acc[i][2]; o.w = acc[i][3];
            }
            *(float4*)&P[gr * N + gc] = o;
        }
    }
}

// ---------------------------------------------------------------------------
// W_out transpose -> fp16
// ---------------------------------------------------------------------------
__global__ void __launch_bounds__(256) wt_kernel(const float* __restrict__ W,
                                                 __half* __restrict__ Wt)
{
    __shared__ float tile[32][33];
    int v0 = blockIdx.x * 32, j0 = blockIdx.y * 32;
    int tx = threadIdx.x & 31, ty = threadIdx.x >> 5;
#pragma unroll
    for (int i = 0; i < 4; i++)
        tile[ty + i * 8][tx] = W[(j0 + ty + i * 8) * VV + v0 + tx];
    __syncthreads();
#pragma unroll
    for (int i = 0; i < 4; i++)
        Wt[(size_t)(v0 + ty + i * 8) * JJ + j0 + tx] = __float2half_rn(tile[tx][ty + i * 8]);
}

// ---------------------------------------------------------------------------
// act kernel: act[row][j] = fp16(tanh(enc[bt][j] + pred[bu][j]))
// hw tanh.approx.f32 (1 MUFU) — act is issue-bound, halves instr count
// ---------------------------------------------------------------------------
__global__ void __launch_bounds__(256) act_kernel(
    const float* __restrict__ enc, const float* __restrict__ pred,
    __half* __restrict__ act)
{
    int idx = blockIdx.x * 256 + threadIdx.x;
    int row = idx / 80;
    int jc  = (idx % 80) * 8;
    int bt  = row / UU;
    int b   = row / (TT * UU);
    int u   = row % UU;

    const float4* ep = (const float4*)&enc [(size_t)bt * JJ + jc];
    const float4* pp = (const float4*)&pred[(size_t)(b * UU + u) * JJ + jc];
    float4 e0 = ep[0], e1 = ep[1];
    float4 p0 = pp[0], p1 = pp[1];

    __half2 h[4];
    h[0] = __floats2half2_rn(hw_tanh(e0.x + p0.x), hw_tanh(e0.y + p0.y));
    h[1] = __floats2half2_rn(hw_tanh(e0.z + p0.z), hw_tanh(e0.w + p0.w));
    h[2] = __floats2half2_rn(hw_tanh(e1.x + p1.x), hw_tanh(e1.y + p1.y));
    h[3] = __floats2half2_rn(hw_tanh(e1.z + p1.z), hw_tanh(e1.w + p1.w));
    *(uint4*)&act[(size_t)row * JJ + jc] = *(uint4*)h;
}

// ---------------------------------------------------------------------------
// persistent GEMM: 512 thr, 16 warps (4x4), warp tile 32x64, CTA 128x256
// continuous cross-tile 4-stage cp.async pipeline (round-9 validated, 580us)
// ---------------------------------------------------------------------------
__global__ void __launch_bounds__(512, 1) gemm_kernel(
    const __half* __restrict__ A, const __half* __restrict__ Bt,
    const float* __restrict__ bias, float* __restrict__ out, int grid_sz)
{
    extern __shared__ __half sm[];

    const int tid  = threadIdx.x;
    const int lane = tid & 31, wid = tid >> 5;
    const int warp_m = wid >> 2, warp_n = wid & 3;     // 4 x 4 warp grid
    const int bid = blockIdx.x;

    // per-thread cp.async lane: r in [0,128), c4 in [0,4)
    const int r = tid >> 2, c4 = tid & 3;
    const uint32_t smbase = smem_u32(sm);
    const uint32_t cpA_off = (uint32_t)(r * LDAH + c4 * 8) * 2;
    const uint32_t cpB_off = (uint32_t)(A_BUF + r * LDAH + c4 * 8) * 2;
    const uint32_t brow2 = (uint32_t)(128 * LDAH) * 2;

    // prefetch for CTA-local chunk counter q: tile = bid + (q/20)*grid_sz
    auto prefetch = [&](int q) {
        const int st_i = q / NCHUNK;
        const int tt = bid + st_i * grid_sz;
        if (tt < NTILES_TOT) {
            const int koff = (q - st_i * NCHUNK) * BK;
            const size_t m0p = (size_t)(tt >> 2) * TILE_M;
            const int n0p = (tt & 3) * TILE_N;
            const uint32_t stg = smbase + (uint32_t)((q & (NSTAGE - 1)) * STAGE_H) * 2;
            const __half* asp = A + (m0p + r) * JJ + c4 * 8 + koff;
            const __half* bsp = Bt + (size_t)(n0p + r) * JJ + c4 * 8 + koff;
            cp16(stg + cpA_off, asp);
            cp16(stg + cpB_off, bsp);
            cp16(stg + cpB_off + brow2, bsp + (size_t)128 * JJ);
        }
        cp_commit();   // always commit to keep group accounting
    };

    // prologue: CTA-local chunks 0..2
#pragma unroll
    for (int s = 0; s < NSTAGE - 1; s++) prefetch(s);

    // ldsm lane decode (validated mapping)
    const int g = lane >> 3, lr = lane & 7;
    const int a_row_off = lr + ((g & 1) << 3);
    const int a_col_off = (g >> 1) << 3;
    const int b_row_off = lr + ((g >> 1) << 3);
    const int b_col_off = (g & 1) << 3;

    const int a_base_row = warp_m * 32 + a_row_off;
    const int b_base_row = warp_n * 64 + b_row_off;

    uint32_t afr[2][2][4];     // [ks][mi]
    uint32_t bfrL[2][4][2];    // [ks][nj 0..3]
    uint32_t bfrH[4][2];       // nj 4..7 (single-buffered, WAR reuse)

    int q = 0;
    for (int tile = bid; tile < NTILES_TOT; tile += grid_sz) {
        const size_t m0 = (size_t)(tile >> 2) * TILE_M;
        const int n0 = (tile & 3) * TILE_N;

        float acc[2][8][4];
#pragma unroll
        for (int i = 0; i < 2; i++)
#pragma unroll
            for (int j = 0; j < 8; j++)
#pragma unroll
                for (int p = 0; p < 4; p++) acc[i][j][p] = 0.f;

        for (int c = 0; c < NCHUNK; c++, q++) {
            cp_wait2();
            __syncthreads();

            const __half* As = sm + (q & (NSTAGE - 1)) * STAGE_H;
            const __half* Bs = As + A_BUF;

            // ---- ks = 0 loads ----
#pragma unroll
            for (int mi = 0; mi < 2; mi++)
                ldsm4(afr[0][mi], &As[(a_base_row + mi * 16) * LDAH + a_col_off]);
#pragma unroll
            for (int j = 0; j < 2; j++) {
                uint32_t r4[4];
                ldsm4(r4, &Bs[(b_base_row + j * 16) * LDAH + b_col_off]);
                bfrL[0][2 * j][0] = r4[0]; bfrL[0][2 * j][1] = r4[1];
                bfrL[0][2 * j + 1][0] = r4[2]; bfrL[0][2 * j + 1][1] = r4[3];
            }
#pragma unroll
            for (int j = 0; j < 2; j++) {
                uint32_t r4[4];
                ldsm4(r4, &Bs[(b_base_row + (j + 2) * 16) * LDAH + b_col_off]);
                bfrH[2 * j][0] = r4[0]; bfrH[2 * j][1] = r4[1];
                bfrH[2 * j + 1][0] = r4[2]; bfrH[2 * j + 1][1] = r4[3];
            }

            // mma ks0 x low half, while loading ks1 A + BL
#pragma unroll
            for (int mi = 0; mi < 2; mi++)
#pragma unroll
                for (int nj = 0; nj < 4; nj++)
                    mma16816(acc[mi][nj], afr[0][mi], bfrL[0][nj]);

#pragma unroll
            for (int mi = 0; mi < 2; mi++)
                ldsm4(afr[1][mi], &As[(a_base_row + mi * 16) * LDAH + 16 + a_col_off]);
#pragma unroll
            for (int j = 0; j < 2; j++) {
                uint32_t r4[4];
                ldsm4(r4, &Bs[(b_base_row + j * 16) * LDAH + 16 + b_col_off]);
                bfrL[1][2 * j][0] = r4[0]; bfrL[1][2 * j][1] = r4[1];
                bfrL[1][2 * j + 1][0] = r4[2]; bfrL[1][2 * j + 1][1] = r4[3];
            }

            // mma ks0 x high half
#pragma unroll
            for (int mi = 0; mi < 2; mi++)
#pragma unroll
                for (int nj = 0; nj < 4; nj++)
                    mma16816(acc[mi][nj + 4], afr[0][mi], bfrH[nj]);

            // load ks1 BH (WAR reuse)
#pragma unroll
            for (int j = 0; j < 2; j++) {
                uint32_t r4[4];
                ldsm4(r4, &Bs[(b_base_row + (j + 2) * 16) * LDAH + 16 + b_col_off]);
                bfrH[2 * j][0] = r4[0]; bfrH[2 * j][1] = r4[1];
                bfrH[2 * j + 1][0] = r4[2]; bfrH[2 * j + 1][1] = r4[3];
            }

            // mma ks1 x low half
#pragma unroll
            for (int mi = 0; mi < 2; mi++)
#pragma unroll
                for (int nj = 0; nj < 4; nj++)
                    mma16816(acc[mi][nj], afr[1][mi], bfrL[1][nj]);

            // issue prefetch for chunk q+3 (possibly next tile; stage (q-1)&3)
            prefetch(q + NSTAGE - 1);

            // mma ks1 x high half
#pragma unroll
            for (int mi = 0; mi < 2; mi++)
#pragma unroll
                for (int nj = 0; nj < 4; nj++)
                    mma16816(acc[mi][nj + 4], afr[1][mi], bfrH[nj]);
        }

        // epilogue (registers only; overlaps in-flight next-tile cp.async)
        const int qr = lane >> 2, qc = (lane & 3) * 2;
        const int colbase = n0 + warp_n * 64;
#pragma unroll
        for (int mi = 0; mi < 2; mi++) {
            size_t row = m0 + warp_m * 32 + mi * 16 + qr;
            float* o0 = out + row * VV + colbase;
            float* o1 = o0 + (size_t)8 * VV;
#pragma unroll
            for (int nj = 0; nj < 8; nj++) {
                int col = nj * 8 + qc;
                float2 bv = *(const float2*)&bias[colbase + col];
                float2 w0 = { acc[mi][nj][0] + bv.x, acc[mi][nj][1] + bv.y };
                float2 w1 = { acc[mi][nj][2] + bv.x, acc[mi][nj][3] + bv.y };
                *(float2*)(o0 + col) = w0;
                *(float2*)(o1 + col) = w1;
            }
        }
    }
}

// ---------------------------------------------------------------------------
extern "C" void kernel_launch(void* const* d_in, const int* in_sizes, int n_in,
                              void* d_out, int out_size)
{
    const float* enc_out  = (const float*)d_in[0];
    const float* pred_out = (const float*)d_in[1];
    const float* W_enc    = (const float*)d_in[2];
    const float* b_enc    = (const float*)d_in[3];
    const float* W_pred   = (const float*)d_in[4];
    const float* W_out    = (const float*)d_in[5];
    const float* b_out    = (const float*)d_in[6];
    float* out = (float*)d_out;

    float *ge, *gp; __half *gw, *ga;
    cudaGetSymbolAddress((void**)&ge, g_enc);
    cudaGetSymbolAddress((void**)&gp, g_pred);
    cudaGetSymbolAddress((void**)&gw, g_wt);
    cudaGetSymbolAddress((void**)&ga, g_act);

    int nsm = 148;
    cudaDeviceGetAttribute(&nsm, cudaDevAttrMultiProcessorCount, 0);

    proj2_kernel<<<380, 256>>>(enc_out, pred_out, W_enc, W_pred, b_enc, ge, gp);
    wt_kernel<<<dim3(VV / 32, JJ / 32), 256>>>(W_out, gw);
    act_kernel<<<(MM * 80) / 256, 256>>>(ge, gp, ga);

    cudaFuncSetAttribute(gemm_kernel, cudaFuncAttributeMaxDynamicSharedMemorySize, SMEM_BYTES);
    gemm_kernel<<<nsm, 512, SMEM_BYTES>>>(ga, gw, b_out, out, nsm);
}